// round 1
// baseline (speedup 1.0000x reference)
#include <cuda_runtime.h>

namespace {

constexpr int Bc = 4, Lc = 2048, Hc = 8, Ec = 64;
constexpr int BM = 64, BN = 64;
constexpr int TS = 68;               // padded stride (floats) for transposed tiles / P tile
constexpr int RE = Hc * Ec;          // 512 floats: stride between consecutive l for fixed (b,h)
constexpr float SCL2E = 0.125f * 1.44269504088896340736f;  // (1/sqrt(64)) * log2(e)

__device__ __forceinline__ float ex2f(float x) {
  float y;
  asm("ex2.approx.ftz.f32 %0, %1;" : "=f"(y) : "f"(x));
  return y;
}

#define SFMA(i, ax)                                                  \
  s[i][0] += (ax) * bb.x; s[i][1] += (ax) * bb.y;                    \
  s[i][2] += (ax) * bb.z; s[i][3] += (ax) * bb.w;

#define PVFMA(i, p, v)                                               \
  acc[i][0] += (p) * (v).x; acc[i][1] += (p) * (v).y;                \
  acc[i][2] += (p) * (v).z; acc[i][3] += (p) * (v).w;

__global__ __launch_bounds__(256, 2)
void hybrid_attn(const float* __restrict__ Q, const float* __restrict__ K,
                 const float* __restrict__ V, float* __restrict__ O) {
  extern __shared__ float smf[];
  float* Qs = smf;                   // [Ec][TS]  (e-major, transposed, pre-scaled)
  float* Ks = Qs + Ec * TS;          // [Ec][TS]
  float* Ps = Ks + Ec * TS;          // [BM][TS]
  float* Vs = Ps + BM * TS;          // [BN][Ec]
  float* Ls = Vs + BN * Ec;          // [BM][4] local-window scores

  const int tid = threadIdx.x;
  const int tx = tid & 15, ty = tid >> 4;
  const int m0 = blockIdx.x * BM;
  const int bh = blockIdx.y;
  const int b = bh >> 3, h = bh & 7;

  const int base = (b * Lc * Hc + h) * Ec;
  const float* Qg = Q + base;
  const float* Kg = K + base;
  const float* Vg = V + base;
  float* Og = O + base;

  // ---- load Q tile transposed into SMEM, pre-scaled by scale*log2e ----
  {
    const int rr0 = tid >> 4;
    const int e4 = (tid & 15) << 2;
    #pragma unroll
    for (int it = 0; it < 4; ++it) {
      const int r = rr0 + it * 16;
      const float4 q = *reinterpret_cast<const float4*>(&Qg[(m0 + r) * RE + e4]);
      Qs[(e4 + 0) * TS + r] = q.x * SCL2E;
      Qs[(e4 + 1) * TS + r] = q.y * SCL2E;
      Qs[(e4 + 2) * TS + r] = q.z * SCL2E;
      Qs[(e4 + 3) * TS + r] = q.w * SCL2E;
    }
  }

  const int r0 = ty << 2;   // 4 query rows owned by this thread
  const int c0 = tx << 2;   // 4 key cols (score phase) / 4 e-cols (PV + output phase)

  float mi[4], li[4], acc[4][4];
  #pragma unroll
  for (int i = 0; i < 4; ++i) {
    mi[i] = -1e30f; li[i] = 0.f;
    #pragma unroll
    for (int k = 0; k < 4; ++k) acc[i][k] = 0.f;
  }

  for (int n0 = 0; n0 < Lc; n0 += BN) {
    __syncthreads();  // previous iteration finished reading Ks/Vs/Ps

    // ---- load K tile (transposed) and V tile (natural) ----
    {
      const int rr0 = tid >> 4;
      const int e4 = (tid & 15) << 2;
      #pragma unroll
      for (int it = 0; it < 4; ++it) {
        const int r = rr0 + it * 16;
        const float4 kk = *reinterpret_cast<const float4*>(&Kg[(n0 + r) * RE + e4]);
        Ks[(e4 + 0) * TS + r] = kk.x;
        Ks[(e4 + 1) * TS + r] = kk.y;
        Ks[(e4 + 2) * TS + r] = kk.z;
        Ks[(e4 + 3) * TS + r] = kk.w;
        const float4 vv = *reinterpret_cast<const float4*>(&Vg[(n0 + r) * RE + e4]);
        *reinterpret_cast<float4*>(&Vs[r * Ec + e4]) = vv;
      }
    }
    __syncthreads();

    // ---- scores: s[4][4] = (scale*log2e) * Q K^T microtile ----
    float s[4][4];
    #pragma unroll
    for (int i = 0; i < 4; ++i)
      #pragma unroll
      for (int k = 0; k < 4; ++k) s[i][k] = 0.f;

    #pragma unroll 16
    for (int e = 0; e < Ec; ++e) {
      const float4 a  = *reinterpret_cast<const float4*>(&Qs[e * TS + r0]);
      const float4 bb = *reinterpret_cast<const float4*>(&Ks[e * TS + c0]);
      SFMA(0, a.x) SFMA(1, a.y) SFMA(2, a.z) SFMA(3, a.w)
    }

    // ---- online softmax update (exp2 domain); row stats redundant across the 16 tx lanes ----
    #pragma unroll
    for (int i = 0; i < 4; ++i) {
      float tm = fmaxf(fmaxf(s[i][0], s[i][1]), fmaxf(s[i][2], s[i][3]));
      #pragma unroll
      for (int off = 8; off; off >>= 1)
        tm = fmaxf(tm, __shfl_xor_sync(0xffffffffu, tm, off));
      const float newm = fmaxf(mi[i], tm);
      const float fac = ex2f(mi[i] - newm);
      float psum = 0.f;
      #pragma unroll
      for (int k = 0; k < 4; ++k) {
        const float p = ex2f(s[i][k] - newm);
        s[i][k] = p;
        psum += p;
      }
      #pragma unroll
      for (int off = 8; off; off >>= 1)
        psum += __shfl_xor_sync(0xffffffffu, psum, off);
      li[i] = li[i] * fac + psum;
      mi[i] = newm;
      #pragma unroll
      for (int k = 0; k < 4; ++k) acc[i][k] *= fac;
      float4 pv = make_float4(s[i][0], s[i][1], s[i][2], s[i][3]);
      *reinterpret_cast<float4*>(&Ps[(r0 + i) * TS + c0]) = pv;
    }
    __syncthreads();

    // ---- PV: acc[4 rows][4 e-cols] += P[rows][j] * V[j][e-cols] ----
    #pragma unroll 4
    for (int j0 = 0; j0 < BN; j0 += 4) {
      const float4 p0 = *reinterpret_cast<const float4*>(&Ps[(r0 + 0) * TS + j0]);
      const float4 p1 = *reinterpret_cast<const float4*>(&Ps[(r0 + 1) * TS + j0]);
      const float4 p2 = *reinterpret_cast<const float4*>(&Ps[(r0 + 2) * TS + j0]);
      const float4 p3 = *reinterpret_cast<const float4*>(&Ps[(r0 + 3) * TS + j0]);
      const float4 v0 = *reinterpret_cast<const float4*>(&Vs[(j0 + 0) * Ec + c0]);
      const float4 v1 = *reinterpret_cast<const float4*>(&Vs[(j0 + 1) * Ec + c0]);
      const float4 v2 = *reinterpret_cast<const float4*>(&Vs[(j0 + 2) * Ec + c0]);
      const float4 v3 = *reinterpret_cast<const float4*>(&Vs[(j0 + 3) * Ec + c0]);
      PVFMA(0, p0.x, v0) PVFMA(1, p1.x, v0) PVFMA(2, p2.x, v0) PVFMA(3, p3.x, v0)
      PVFMA(0, p0.y, v1) PVFMA(1, p1.y, v1) PVFMA(2, p2.y, v1) PVFMA(3, p3.y, v1)
      PVFMA(0, p0.z, v2) PVFMA(1, p1.z, v2) PVFMA(2, p2.z, v2) PVFMA(3, p3.z, v2)
      PVFMA(0, p0.w, v3) PVFMA(1, p1.w, v3) PVFMA(2, p2.w, v3) PVFMA(3, p3.w, v3)
    }
  }

  // ---- local branch: scores for j in [i-2, i+1], one (row, jj) per thread ----
  __syncthreads();
  {
    const int lr = tid >> 2;       // 0..63
    const int jj = tid & 3;
    const int ig = m0 + lr;
    const int j = ig - 2 + jj;
    float sc = -1e30f;
    if (j >= 0 && j < Lc) {
      float dot = 0.f;
      #pragma unroll
      for (int e4 = 0; e4 < Ec; e4 += 4) {
        const float4 kk = *reinterpret_cast<const float4*>(&Kg[j * RE + e4]);
        dot += Qs[(e4 + 0) * TS + lr] * kk.x
             + Qs[(e4 + 1) * TS + lr] * kk.y
             + Qs[(e4 + 2) * TS + lr] * kk.z
             + Qs[(e4 + 3) * TS + lr] * kk.w;
      }
      sc = dot;  // already includes scale*log2e via Qs
    }
    Ls[(lr << 2) + jj] = sc;
  }
  __syncthreads();

  // ---- combine global (normalized) + local branch, write output ----
  #pragma unroll
  for (int i = 0; i < 4; ++i) {
    const int r = r0 + i;
    const int ig = m0 + r;
    const float4 lsc = *reinterpret_cast<const float4*>(&Ls[r << 2]);
    const float mx = fmaxf(fmaxf(lsc.x, lsc.y), fmaxf(lsc.z, lsc.w));
    float w[4];
    w[0] = ex2f(lsc.x - mx); w[1] = ex2f(lsc.y - mx);
    w[2] = ex2f(lsc.z - mx); w[3] = ex2f(lsc.w - mx);
    const float winv = 1.f / (w[0] + w[1] + w[2] + w[3]);
    const float invl = 1.f / li[i];
    float4 outv = make_float4(acc[i][0] * invl, acc[i][1] * invl,
                              acc[i][2] * invl, acc[i][3] * invl);
    #pragma unroll
    for (int jj = 0; jj < 4; ++jj) {
      const int j = ig - 2 + jj;
      if (j >= 0 && j < Lc) {
        const float wj = w[jj] * winv;
        const float4 v = *reinterpret_cast<const float4*>(&Vg[j * RE + c0]);
        outv.x += wj * v.x; outv.y += wj * v.y;
        outv.z += wj * v.z; outv.w += wj * v.w;
      }
    }
    *reinterpret_cast<float4*>(&Og[ig * RE + c0]) = outv;
  }
}

}  // namespace

extern "C" void kernel_launch(void* const* d_in, const int* in_sizes, int n_in,
                              void* d_out, int out_size) {
  const float* Q = (const float*)d_in[0];
  const float* K = (const float*)d_in[1];
  const float* V = (const float*)d_in[2];
  float* O = (float*)d_out;

  const size_t smem = (size_t)(Ec * TS * 2 + BM * TS + BN * Ec + BM * 4) * sizeof(float);
  cudaFuncSetAttribute(hybrid_attn, cudaFuncAttributeMaxDynamicSharedMemorySize, (int)smem);

  dim3 grid(Lc / BM, Bc * Hc);
  hybrid_attn<<<grid, 256, smem>>>(Q, K, V, O);
}

// round 2
// speedup vs baseline: 1.1510x; 1.1510x over previous
#include <cuda_runtime.h>

namespace {

using ull = unsigned long long;

constexpr int Lc = 2048, Hc = 8, Ec = 64;
constexpr int BM = 64, BN = 128;
constexpr int TSQ = 68;              // Qs row stride (floats), e-major
constexpr int TSK = 132;             // Ks/Ps row stride (floats)
constexpr int RE = Hc * Ec;          // 512
constexpr float SCL2E = 0.125f * 1.44269504088896340736f;

// smem offsets in floats
constexpr int OFF_Q = 0;                         // [64][TSQ]
constexpr int OFF_KP = OFF_Q + Ec * TSQ;         // [64][TSK]  K-tile, then aliased as P-tile
constexpr int OFF_V = OFF_KP + 64 * TSK;         // [128][64]
constexpr int OFF_L = OFF_V + BN * Ec;           // [64][4]
constexpr int SMEM_FLOATS = OFF_L + BM * 4;

__device__ __forceinline__ float ex2f(float x) {
  float y; asm("ex2.approx.ftz.f32 %0, %1;" : "=f"(y) : "f"(x)); return y;
}
__device__ __forceinline__ void fma2(ull& d, ull a, ull b) {
  asm("fma.rn.f32x2 %0, %1, %2, %0;" : "+l"(d) : "l"(a), "l"(b));
}
__device__ __forceinline__ void mul2(ull& d, ull a) {
  asm("mul.rn.f32x2 %0, %0, %1;" : "+l"(d) : "l"(a));
}
__device__ __forceinline__ ull bcast2(float x) {
  ull r; asm("mov.b64 %0, {%1, %1};" : "=l"(r) : "f"(x)); return r;
}
__device__ __forceinline__ void unp2(ull v, float& lo, float& hi) {
  asm("mov.b64 {%0, %1}, %2;" : "=f"(lo), "=f"(hi) : "l"(v));
}

__global__ __launch_bounds__(128, 2)
void hybrid_attn(const float* __restrict__ Q, const float* __restrict__ K,
                 const float* __restrict__ V, float* __restrict__ O) {
  extern __shared__ float smf[];
  float* Qs = smf + OFF_Q;
  float* KP = smf + OFF_KP;
  float* Vs = smf + OFF_V;
  float* Ls = smf + OFF_L;

  const int tid = threadIdx.x;
  const int tx = tid & 15;           // 16 col groups
  const int ty = tid >> 4;           // 8 row groups
  const int r0 = ty << 3;            // 8 query rows
  const int c0 = tx << 2;            // cols [4tx..4tx+3]
  const int c1 = 64 + c0;            // cols [64+4tx..+3]

  const int m0 = blockIdx.x * BM;
  const int bh = blockIdx.y;
  const int base = ((bh >> 3) * Lc * Hc + (bh & 7)) * Ec;
  const float* Qg = Q + base;
  const float* Kg = K + base;
  const float* Vg = V + base;
  float* Og = O + base;

  const int le4 = (tid & 15) << 2;   // loader e-chunk
  const int lr = tid >> 4;           // loader row base

  // ---- prologue: Q tile -> Qs (e-major, scaled) ----
  #pragma unroll
  for (int it = 0; it < 8; ++it) {
    const int r = lr + it * 8;
    const float4 q = *reinterpret_cast<const float4*>(&Qg[(m0 + r) * RE + le4]);
    Qs[(le4 + 0) * TSQ + r] = q.x * SCL2E;
    Qs[(le4 + 1) * TSQ + r] = q.y * SCL2E;
    Qs[(le4 + 2) * TSQ + r] = q.z * SCL2E;
    Qs[(le4 + 3) * TSQ + r] = q.w * SCL2E;
  }

  float mi[8], li[8];
  ull acc[8][2];
  #pragma unroll
  for (int i = 0; i < 8; ++i) { mi[i] = -1e30f; li[i] = 0.f; acc[i][0] = 0ull; acc[i][1] = 0ull; }

  for (int n0 = 0; n0 < Lc; n0 += BN) {
    __syncthreads();  // prev PV done reading KP(=Ps)/Vs

    // ---- load K (transposed into KP) and V (natural) ----
    #pragma unroll
    for (int it = 0; it < 16; ++it) {
      const int r = lr + it * 8;
      const float4 kk = *reinterpret_cast<const float4*>(&Kg[(n0 + r) * RE + le4]);
      KP[(le4 + 0) * TSK + r] = kk.x;
      KP[(le4 + 1) * TSK + r] = kk.y;
      KP[(le4 + 2) * TSK + r] = kk.z;
      KP[(le4 + 3) * TSK + r] = kk.w;
      const float4 vv = *reinterpret_cast<const float4*>(&Vg[(n0 + r) * RE + le4]);
      *reinterpret_cast<float4*>(&Vs[r * Ec + le4]) = vv;
    }
    __syncthreads();

    // ---- QK^T: s[8 rows][8 cols as 4 f32x2 pairs] ----
    ull s[8][4];
    #pragma unroll
    for (int i = 0; i < 8; ++i)
      #pragma unroll
      for (int p = 0; p < 4; ++p) s[i][p] = 0ull;

    #pragma unroll 4
    for (int e = 0; e < Ec; ++e) {
      const ulonglong2 b0 = *reinterpret_cast<const ulonglong2*>(&KP[e * TSK + c0]);
      const ulonglong2 b1 = *reinterpret_cast<const ulonglong2*>(&KP[e * TSK + c1]);
      const float4 a0 = *reinterpret_cast<const float4*>(&Qs[e * TSQ + r0]);
      const float4 a1 = *reinterpret_cast<const float4*>(&Qs[e * TSQ + r0 + 4]);
      ull aa;
      aa = bcast2(a0.x); fma2(s[0][0], aa, b0.x); fma2(s[0][1], aa, b0.y); fma2(s[0][2], aa, b1.x); fma2(s[0][3], aa, b1.y);
      aa = bcast2(a0.y); fma2(s[1][0], aa, b0.x); fma2(s[1][1], aa, b0.y); fma2(s[1][2], aa, b1.x); fma2(s[1][3], aa, b1.y);
      aa = bcast2(a0.z); fma2(s[2][0], aa, b0.x); fma2(s[2][1], aa, b0.y); fma2(s[2][2], aa, b1.x); fma2(s[2][3], aa, b1.y);
      aa = bcast2(a0.w); fma2(s[3][0], aa, b0.x); fma2(s[3][1], aa, b0.y); fma2(s[3][2], aa, b1.x); fma2(s[3][3], aa, b1.y);
      aa = bcast2(a1.x); fma2(s[4][0], aa, b0.x); fma2(s[4][1], aa, b0.y); fma2(s[4][2], aa, b1.x); fma2(s[4][3], aa, b1.y);
      aa = bcast2(a1.y); fma2(s[5][0], aa, b0.x); fma2(s[5][1], aa, b0.y); fma2(s[5][2], aa, b1.x); fma2(s[5][3], aa, b1.y);
      aa = bcast2(a1.z); fma2(s[6][0], aa, b0.x); fma2(s[6][1], aa, b0.y); fma2(s[6][2], aa, b1.x); fma2(s[6][3], aa, b1.y);
      aa = bcast2(a1.w); fma2(s[7][0], aa, b0.x); fma2(s[7][1], aa, b0.y); fma2(s[7][2], aa, b1.x); fma2(s[7][3], aa, b1.y);
    }
    __syncthreads();  // all threads done reading KP as K-tile

    // ---- online softmax; write P into KP (aliased) ----
    #pragma unroll
    for (int i = 0; i < 8; ++i) {
      float v0, v1, v2, v3, v4, v5, v6, v7;
      unp2(s[i][0], v0, v1); unp2(s[i][1], v2, v3);
      unp2(s[i][2], v4, v5); unp2(s[i][3], v6, v7);
      float tm = fmaxf(fmaxf(fmaxf(v0, v1), fmaxf(v2, v3)),
                       fmaxf(fmaxf(v4, v5), fmaxf(v6, v7)));
      #pragma unroll
      for (int off = 8; off; off >>= 1)
        tm = fmaxf(tm, __shfl_xor_sync(0xffffffffu, tm, off));
      const float newm = fmaxf(mi[i], tm);
      const float fac = ex2f(mi[i] - newm);
      v0 = ex2f(v0 - newm); v1 = ex2f(v1 - newm); v2 = ex2f(v2 - newm); v3 = ex2f(v3 - newm);
      v4 = ex2f(v4 - newm); v5 = ex2f(v5 - newm); v6 = ex2f(v6 - newm); v7 = ex2f(v7 - newm);
      float psum = (v0 + v1) + (v2 + v3) + (v4 + v5) + (v6 + v7);
      #pragma unroll
      for (int off = 8; off; off >>= 1)
        psum += __shfl_xor_sync(0xffffffffu, psum, off);
      li[i] = li[i] * fac + psum;
      mi[i] = newm;
      const ull fv = bcast2(fac);
      mul2(acc[i][0], fv); mul2(acc[i][1], fv);
      *reinterpret_cast<float4*>(&KP[(r0 + i) * TSK + c0]) = make_float4(v0, v1, v2, v3);
      *reinterpret_cast<float4*>(&KP[(r0 + i) * TSK + c1]) = make_float4(v4, v5, v6, v7);
    }
    __syncthreads();

    // ---- PV: acc[8 rows][4 e-cols as 2 pairs] ----
    #pragma unroll 2
    for (int j0 = 0; j0 < BN; j0 += 4) {
      const ulonglong2 w0 = *reinterpret_cast<const ulonglong2*>(&Vs[(j0 + 0) * Ec + c0]);
      const ulonglong2 w1 = *reinterpret_cast<const ulonglong2*>(&Vs[(j0 + 1) * Ec + c0]);
      const ulonglong2 w2 = *reinterpret_cast<const ulonglong2*>(&Vs[(j0 + 2) * Ec + c0]);
      const ulonglong2 w3 = *reinterpret_cast<const ulonglong2*>(&Vs[(j0 + 3) * Ec + c0]);
      #pragma unroll
      for (int i = 0; i < 8; ++i) {
        const float4 p = *reinterpret_cast<const float4*>(&KP[(r0 + i) * TSK + j0]);
        ull aa;
        aa = bcast2(p.x); fma2(acc[i][0], aa, w0.x); fma2(acc[i][1], aa, w0.y);
        aa = bcast2(p.y); fma2(acc[i][0], aa, w1.x); fma2(acc[i][1], aa, w1.y);
        aa = bcast2(p.z); fma2(acc[i][0], aa, w2.x); fma2(acc[i][1], aa, w2.y);
        aa = bcast2(p.w); fma2(acc[i][0], aa, w3.x); fma2(acc[i][1], aa, w3.y);
      }
    }
  }

  // ---- local branch scores: rows m0..m0+63, offsets jj in [0,4) ----
  __syncthreads();
  {
    const int row = tid >> 1;            // 0..63
    const int jbase = (tid & 1) << 1;    // 0 or 2
    #pragma unroll
    for (int t = 0; t < 2; ++t) {
      const int jj = jbase + t;
      const int ig = m0 + row;
      const int j = ig - 2 + jj;
      float sc = -1e30f;
      if (j >= 0 && j < Lc) {
        float dot = 0.f;
        #pragma unroll
        for (int e4 = 0; e4 < Ec; e4 += 4) {
          const float4 kk = *reinterpret_cast<const float4*>(&Kg[j * RE + e4]);
          dot += Qs[(e4 + 0) * TSQ + row] * kk.x
               + Qs[(e4 + 1) * TSQ + row] * kk.y
               + Qs[(e4 + 2) * TSQ + row] * kk.z
               + Qs[(e4 + 3) * TSQ + row] * kk.w;
        }
        sc = dot;  // already includes scale*log2e
      }
      Ls[(row << 2) + jj] = sc;
    }
  }
  __syncthreads();

  // ---- combine global + local, write output ----
  #pragma unroll
  for (int i = 0; i < 8; ++i) {
    const int r = r0 + i;
    const int ig = m0 + r;
    const float4 lsc = *reinterpret_cast<const float4*>(&Ls[r << 2]);
    const float mx = fmaxf(fmaxf(lsc.x, lsc.y), fmaxf(lsc.z, lsc.w));
    float w[4];
    w[0] = ex2f(lsc.x - mx); w[1] = ex2f(lsc.y - mx);
    w[2] = ex2f(lsc.z - mx); w[3] = ex2f(lsc.w - mx);
    const float winv = 1.f / (w[0] + w[1] + w[2] + w[3]);
    const float invl = 1.f / li[i];
    float o0, o1, o2, o3;
    unp2(acc[i][0], o0, o1); unp2(acc[i][1], o2, o3);
    float4 outv = make_float4(o0 * invl, o1 * invl, o2 * invl, o3 * invl);
    #pragma unroll
    for (int jj = 0; jj < 4; ++jj) {
      const int j = ig - 2 + jj;
      if (j >= 0 && j < Lc) {
        const float wj = w[jj] * winv;
        const float4 v = *reinterpret_cast<const float4*>(&Vg[j * RE + c0]);
        outv.x += wj * v.x; outv.y += wj * v.y;
        outv.z += wj * v.z; outv.w += wj * v.w;
      }
    }
    *reinterpret_cast<float4*>(&Og[ig * RE + c0]) = outv;
  }
}

}  // namespace

extern "C" void kernel_launch(void* const* d_in, const int* in_sizes, int n_in,
                              void* d_out, int out_size) {
  const float* Q = (const float*)d_in[0];
  const float* K = (const float*)d_in[1];
  const float* V = (const float*)d_in[2];
  float* O = (float*)d_out;

  const size_t smem = (size_t)SMEM_FLOATS * sizeof(float);
  cudaFuncSetAttribute(hybrid_attn, cudaFuncAttributeMaxDynamicSharedMemorySize, (int)smem);

  dim3 grid(Lc / BM, 4 * Hc);
  hybrid_attn<<<grid, 128, smem>>>(Q, K, V, O);
}